// round 2
// baseline (speedup 1.0000x reference)
#include <cuda_runtime.h>
#include <math.h>
#include <stdint.h>

// Problem constants
#define DD     1024
#define NB     64
#define SS     36
#define LMAXC  32
#define MROWS  (NB * SS)      // 2304 image-region rows
#define NCAPR  (NB * LMAXC)   // 2048 caption-word rows

// Device scratch (no runtime allocation allowed)
__device__ float g_E[NCAPR * DD];        // energy = cap @ W^T      (8 MB)
__device__ float g_A[MROWS * NCAPR];     // attn raw = img @ E^T    (18.9 MB)
__device__ float g_C[MROWS * NCAPR];     // img @ cap^T             (18.9 MB)
__device__ float g_G[NB * SS * SS];      // per-image Gram matrices
__device__ float g_w1[NCAPR];            // caption word norms

// ---------------------------------------------------------------------------
// packed f32x2 helpers (exact fp32, 2 MACs per issue on the fma pipe)
// ---------------------------------------------------------------------------
__device__ __forceinline__ unsigned long long pk2(float lo, float hi) {
    unsigned long long r;
    asm("mov.b64 %0, {%1, %2};" : "=l"(r) : "f"(lo), "f"(hi));
    return r;
}
__device__ __forceinline__ void fma2(unsigned long long& d,
                                     unsigned long long a,
                                     unsigned long long b) {
    asm("fma.rn.f32x2 %0, %1, %2, %0;" : "+l"(d) : "l"(a), "l"(b));
}
__device__ __forceinline__ void upk2(unsigned long long v, float& lo, float& hi) {
    asm("mov.b64 {%0, %1}, %2;" : "=f"(lo), "=f"(hi) : "l"(v));
}

// ---------------------------------------------------------------------------
// warp reduction helpers
// ---------------------------------------------------------------------------
__device__ __forceinline__ float wsum(float v) {
#pragma unroll
    for (int o = 16; o > 0; o >>= 1) v += __shfl_xor_sync(0xffffffffu, v, o);
    return v;
}
__device__ __forceinline__ float wmax(float v) {
#pragma unroll
    for (int o = 16; o > 0; o >>= 1) v = fmaxf(v, __shfl_xor_sync(0xffffffffu, v, o));
    return v;
}

// ---------------------------------------------------------------------------
// NT GEMM: Cm[m,n] = sum_k A[m,k] * B[n,k]   (both row-major, K contiguous)
// 128x128 tile, BK=16, 256 threads, 8x8 microtile, packed f32x2 inner product.
// All problem dims are multiples of the tile sizes -> no bounds checks.
// ---------------------------------------------------------------------------
#define BM 128
#define BN 128
#define BKC 16

__global__ __launch_bounds__(256, 2)
void gemm_nt(const float* __restrict__ A, const float* __restrict__ B,
             float* __restrict__ Cm, int M, int N, int K)
{
    __shared__ __align__(16) float As[BKC][BM + 4];
    __shared__ __align__(16) float Bs[BKC][BN + 4];

    const int t  = threadIdx.x;
    const int tx = t & 15;
    const int ty = t >> 4;
    const int m0 = blockIdx.y * BM;
    const int n0 = blockIdx.x * BN;
    const int lr = t >> 2;           // 0..63
    const int lk = (t & 3) << 2;     // 0,4,8,12

    const float* Ap = A + (size_t)(m0 + lr) * K + lk;
    const float* Bp = B + (size_t)(n0 + lr) * K + lk;
    const int rowstep = 64 * K;

    unsigned long long accp[8][4];
#pragma unroll
    for (int i = 0; i < 8; ++i)
#pragma unroll
        for (int j = 0; j < 4; ++j) accp[i][j] = 0ull;

    float4 pa0 = *(const float4*)(Ap);
    float4 pa1 = *(const float4*)(Ap + rowstep);
    float4 pb0 = *(const float4*)(Bp);
    float4 pb1 = *(const float4*)(Bp + rowstep);

    for (int kc = 0; kc < K; kc += BKC) {
        As[lk + 0][lr]      = pa0.x; As[lk + 1][lr]      = pa0.y;
        As[lk + 2][lr]      = pa0.z; As[lk + 3][lr]      = pa0.w;
        As[lk + 0][lr + 64] = pa1.x; As[lk + 1][lr + 64] = pa1.y;
        As[lk + 2][lr + 64] = pa1.z; As[lk + 3][lr + 64] = pa1.w;
        Bs[lk + 0][lr]      = pb0.x; Bs[lk + 1][lr]      = pb0.y;
        Bs[lk + 2][lr]      = pb0.z; Bs[lk + 3][lr]      = pb0.w;
        Bs[lk + 0][lr + 64] = pb1.x; Bs[lk + 1][lr + 64] = pb1.y;
        Bs[lk + 2][lr + 64] = pb1.z; Bs[lk + 3][lr + 64] = pb1.w;
        __syncthreads();

        if (kc + BKC < K) {
            pa0 = *(const float4*)(Ap + kc + BKC);
            pa1 = *(const float4*)(Ap + kc + BKC + rowstep);
            pb0 = *(const float4*)(Bp + kc + BKC);
            pb1 = *(const float4*)(Bp + kc + BKC + rowstep);
        }

#pragma unroll 4
        for (int k = 0; k < BKC; ++k) {
            float4 a0 = *(const float4*)(&As[k][ty * 8]);
            float4 a1 = *(const float4*)(&As[k][ty * 8 + 4]);
            float4 b0 = *(const float4*)(&Bs[k][tx * 8]);
            float4 b1 = *(const float4*)(&Bs[k][tx * 8 + 4]);
            unsigned long long bp[4];
            bp[0] = pk2(b0.x, b0.y); bp[1] = pk2(b0.z, b0.w);
            bp[2] = pk2(b1.x, b1.y); bp[3] = pk2(b1.z, b1.w);
            float av[8] = {a0.x, a0.y, a0.z, a0.w, a1.x, a1.y, a1.z, a1.w};
#pragma unroll
            for (int i2 = 0; i2 < 8; ++i2) {
                unsigned long long ap = pk2(av[i2], av[i2]);
                fma2(accp[i2][0], ap, bp[0]);
                fma2(accp[i2][1], ap, bp[1]);
                fma2(accp[i2][2], ap, bp[2]);
                fma2(accp[i2][3], ap, bp[3]);
            }
        }
        __syncthreads();
    }

#pragma unroll
    for (int i = 0; i < 8; ++i) {
        float c[8];
#pragma unroll
        for (int j = 0; j < 4; ++j) upk2(accp[i][j], c[2 * j], c[2 * j + 1]);
        float* dst = Cm + (size_t)(m0 + ty * 8 + i) * N + n0 + tx * 8;
        *(float4*)(dst)     = make_float4(c[0], c[1], c[2], c[3]);
        *(float4*)(dst + 4) = make_float4(c[4], c[5], c[6], c[7]);
    }
}

// ---------------------------------------------------------------------------
// Per-image Gram matrices: G[b][s1][s2] = img[b,s1,:] . img[b,s2,:]
// ---------------------------------------------------------------------------
__global__ __launch_bounds__(256)
void gram_kernel(const float* __restrict__ img)
{
    const int b = blockIdx.x;
    const int t = threadIdx.x;
    __shared__ float sI[SS][65];   // K-chunk of 64, padded against conflicts

    float acc[6] = {0.f, 0.f, 0.f, 0.f, 0.f, 0.f};

    for (int kc = 0; kc < DD; kc += 64) {
        for (int idx = t; idx < SS * 64; idx += 256) {
            int r = idx >> 6, k = idx & 63;
            sI[r][k] = img[(size_t)(b * SS + r) * DD + kc + k];
        }
        __syncthreads();
        for (int p = t, j = 0; p < SS * SS; p += 256, ++j) {
            int s1 = p / SS, s2 = p % SS;
            float sum = 0.f;
#pragma unroll
            for (int k = 0; k < 64; ++k) sum = fmaf(sI[s1][k], sI[s2][k], sum);
            acc[j] += sum;
        }
        __syncthreads();
    }
    for (int p = t, j = 0; p < SS * SS; p += 256, ++j)
        g_G[b * SS * SS + p] = acc[j];
}

// ---------------------------------------------------------------------------
// Caption word norms: g_w1[r] = ||cap_flat[r,:]||
// ---------------------------------------------------------------------------
__global__ __launch_bounds__(256)
void w1_kernel(const float* __restrict__ cap)
{
    const int row  = blockIdx.x * 8 + (threadIdx.x >> 5);
    const int lane = threadIdx.x & 31;
    const float* p = cap + (size_t)row * DD;
    float s = 0.f;
    for (int k = lane; k < DD; k += 32) { float v = p[k]; s = fmaf(v, v, s); }
    s = wsum(s);
    if (lane == 0) g_w1[row] = sqrtf(s);
}

// ---------------------------------------------------------------------------
// Per-(image b, caption i) epilogue: leaky-relu + mask + ragged L2 norm,
// softmax over regions, w12 via C tile, ||wctx||^2 via Gram quadratic form,
// cosine sim, masked LogSumExp.
// ---------------------------------------------------------------------------
__global__ __launch_bounds__(256)
void pair_kernel(const int* __restrict__ cap_lens, float* __restrict__ out)
{
    const int i = blockIdx.x;    // caption
    const int b = blockIdx.y;    // image
    const int t = threadIdx.x;
    const int w = t >> 5, lane = t & 31;
    const int len = cap_lens[i];

    __shared__ float att[SS][33];       // normalized attn, [s][l]
    __shared__ float cw[SS][33];        // C tile, [s][l]
    __shared__ float aw[LMAXC][SS];     // softmax attn, [l][s]
    __shared__ float sG[SS * SS];
    __shared__ float rs[LMAXC];

    // Load Gram (coalesced)
    for (int idx = t; idx < SS * SS; idx += 256) sG[idx] = g_G[b * SS * SS + idx];

    // Phase 1: load A tile, leaky-relu(0.1), mask padded words, L2-normalize
    // over the word axis per region s. Also stage the C tile. Warp per s.
    for (int s = w; s < SS; s += 8) {
        float v = g_A[(size_t)(b * SS + s) * NCAPR + i * LMAXC + lane];
        v = v > 0.f ? v : 0.1f * v;
        if (lane >= len) v = 0.f;
        float ssq = wsum(v * v);
        att[s][lane] = v / (sqrtf(ssq) + 1e-8f);
        cw[s][lane]  = g_C[(size_t)(b * SS + s) * NCAPR + i * LMAXC + lane];
    }
    __syncthreads();

    // Phase 2: softmax over regions (x9), warp per word l. Lane covers
    // s = lane, and s = 32+lane for lane < 4.
    for (int l = w; l < LMAXC; l += 8) {
        float v0 = att[lane][l];
        float v1 = (lane < 4) ? att[32 + lane][l] : 0.f;
        float z0 = 9.0f * v0;
        float z1 = (lane < 4) ? 9.0f * v1 : -1e30f;
        float m  = wmax(fmaxf(z0, z1));
        float e0 = expf(z0 - m);
        float e1 = (lane < 4) ? expf(z1 - m) : 0.f;
        float inv = 1.0f / wsum(e0 + e1);
        aw[l][lane] = e0 * inv;
        if (lane < 4) aw[l][32 + lane] = e1 * inv;
    }
    __syncthreads();

    // Phase 3: w12[l] = sum_s a[l,s]*C[s,l];  w2sq[l] = a_l^T G a_l
    for (int l = w; l < LMAXC; l += 8) {
        float a0 = aw[l][lane];
        float a1 = (lane < 4) ? aw[l][32 + lane] : 0.f;
        float c0 = cw[lane][l];
        float c1 = (lane < 4) ? cw[32 + lane][l] : 0.f;
        float w12 = wsum(a0 * c0 + a1 * c1);

        float t0 = 0.f, t1 = 0.f;
#pragma unroll
        for (int s = 0; s < SS; ++s) {
            float av = aw[l][s];                 // broadcast
            t0 = fmaf(av, sG[s * SS + lane], t0);
            if (lane < 4) t1 = fmaf(av, sG[s * SS + 32 + lane], t1);
        }
        float w2sq = wsum(t0 * a0 + t1 * a1);

        if (lane == 0) {
            float denom = fmaxf(g_w1[i * LMAXC + l] * sqrtf(fmaxf(w2sq, 0.f)), 1e-8f);
            rs[l] = w12 / denom;
        }
    }
    __syncthreads();

    // Phase 4: masked LogSumExp over valid words, /LAMBDA_LSE
    if (w == 0) {
        float z = (lane < len) ? rs[lane] * 6.0f : -1e30f;
        float m = wmax(z);
        float e = (lane < len) ? expf(z - m) : 0.f;
        float ssum = wsum(e);
        if (lane == 0) out[b * NB + i] = (m + logf(ssum)) / 6.0f;
    }
}

// ---------------------------------------------------------------------------
extern "C" void kernel_launch(void* const* d_in, const int* in_sizes, int n_in,
                              void* d_out, int out_size)
{
    const float* images   = (const float*)d_in[0];  // (64,36,1024)
    const float* captions = (const float*)d_in[1];  // (64,32,1024)
    const int*   cap_lens = (const int*)  d_in[2];  // (64,)
    const float* W_g      = (const float*)d_in[3];  // (1024,1024)
    float* out = (float*)d_out;                     // (64,64)

    float *pE, *pA, *pC;
    cudaGetSymbolAddress((void**)&pE, g_E);
    cudaGetSymbolAddress((void**)&pA, g_A);
    cudaGetSymbolAddress((void**)&pC, g_C);

    // GEMM1: E = cap @ W^T        (2048 x 1024 x 1024)
    gemm_nt<<<dim3(DD / BN, NCAPR / BM), 256>>>(captions, W_g, pE, NCAPR, DD, DD);
    // GEMM2: A = img @ E^T        (2304 x 2048 x 1024)
    gemm_nt<<<dim3(NCAPR / BN, MROWS / BM), 256>>>(images, pE, pA, MROWS, NCAPR, DD);
    // GEMM3: C = img @ cap^T      (2304 x 2048 x 1024)
    gemm_nt<<<dim3(NCAPR / BN, MROWS / BM), 256>>>(images, captions, pC, MROWS, NCAPR, DD);
    // Gram matrices + caption norms (independent, cheap)
    gram_kernel<<<NB, 256>>>(images);
    w1_kernel<<<NCAPR / 8, 256>>>(captions);
    // Fused epilogue: one CTA per (image, caption) pair
    pair_kernel<<<dim3(NB, NB), 256>>>(cap_lens, out);
}

// round 7
// speedup vs baseline: 2.2861x; 2.2861x over previous
#include <cuda_runtime.h>
#include <cuda_bf16.h>
#include <math.h>
#include <stdint.h>

// Problem constants
#define DD     1024
#define NB     64
#define SS     36
#define LMAXC  32
#define MROWS  (NB * SS)      // 2304
#define NCAPR  (NB * LMAXC)   // 2048

// ---------------------------------------------------------------------------
// Device scratch (no runtime allocation allowed)
// ---------------------------------------------------------------------------
__device__ float g_E[NCAPR * DD];
__device__ float g_A[MROWS * NCAPR];
__device__ float g_C[MROWS * NCAPR];
__device__ float g_G[NB * SS * SS];
__device__ float g_w1[NCAPR];
__device__ __nv_bfloat16 g_imgH[MROWS * DD], g_imgL[MROWS * DD];
__device__ __nv_bfloat16 g_capH[NCAPR * DD], g_capL[NCAPR * DD];
__device__ __nv_bfloat16 g_WH[DD * DD],     g_WL[DD * DD];
__device__ __nv_bfloat16 g_EH[NCAPR * DD],  g_EL[NCAPR * DD];

// ---------------------------------------------------------------------------
// helpers
// ---------------------------------------------------------------------------
__device__ __forceinline__ uint32_t smem_u32(const void* p) {
    uint32_t a;
    asm("{ .reg .u64 t; cvta.to.shared.u64 t, %1; cvt.u32.u64 %0, t; }" : "=r"(a) : "l"(p));
    return a;
}
__device__ __forceinline__ void cp_async16(uint32_t dst, const void* src) {
    asm volatile("cp.async.cg.shared.global [%0], [%1], 16;" :: "r"(dst), "l"(src));
}
#define CP_COMMIT() asm volatile("cp.async.commit_group;" ::: "memory")
#define CP_WAIT(n)  asm volatile("cp.async.wait_group %0;" :: "n"(n) : "memory")

__device__ __forceinline__ void ldm_x4(uint32_t* r, uint32_t addr) {
    asm volatile("ldmatrix.sync.aligned.m8n8.x4.shared.b16 {%0,%1,%2,%3}, [%4];"
                 : "=r"(r[0]), "=r"(r[1]), "=r"(r[2]), "=r"(r[3]) : "r"(addr));
}
__device__ __forceinline__ void mma16816(float* d, const uint32_t* a,
                                         const uint32_t* b) {
    asm volatile(
        "mma.sync.aligned.m16n8k16.row.col.f32.bf16.bf16.f32 "
        "{%0,%1,%2,%3}, {%4,%5,%6,%7}, {%8,%9}, {%0,%1,%2,%3};"
        : "+f"(d[0]), "+f"(d[1]), "+f"(d[2]), "+f"(d[3])
        : "r"(a[0]), "r"(a[1]), "r"(a[2]), "r"(a[3]), "r"(b[0]), "r"(b[1]));
}

__device__ __forceinline__ float wsum(float v) {
#pragma unroll
    for (int o = 16; o > 0; o >>= 1) v += __shfl_xor_sync(0xffffffffu, v, o);
    return v;
}
__device__ __forceinline__ float wmax(float v) {
#pragma unroll
    for (int o = 16; o > 0; o >>= 1) v = fmaxf(v, __shfl_xor_sync(0xffffffffu, v, o));
    return v;
}

// ---------------------------------------------------------------------------
// split: fp32 -> (bf16 hi, bf16 lo), lo = bf16(x - float(hi))
// ---------------------------------------------------------------------------
__global__ __launch_bounds__(256)
void split_kernel(const float* __restrict__ x, __nv_bfloat16* __restrict__ hi,
                  __nv_bfloat16* __restrict__ lo, int n)
{
    int i = (blockIdx.x * 256 + threadIdx.x) * 4;
    if (i >= n) return;
    float4 v = *(const float4*)(x + i);
    __nv_bfloat16 h0 = __float2bfloat16(v.x), h1 = __float2bfloat16(v.y);
    __nv_bfloat16 h2 = __float2bfloat16(v.z), h3 = __float2bfloat16(v.w);
    __nv_bfloat16 l0 = __float2bfloat16(v.x - __bfloat162float(h0));
    __nv_bfloat16 l1 = __float2bfloat16(v.y - __bfloat162float(h1));
    __nv_bfloat16 l2 = __float2bfloat16(v.z - __bfloat162float(h2));
    __nv_bfloat16 l3 = __float2bfloat16(v.w - __bfloat162float(h3));
    *(__nv_bfloat162*)(hi + i)     = __nv_bfloat162(h0, h1);
    *(__nv_bfloat162*)(hi + i + 2) = __nv_bfloat162(h2, h3);
    *(__nv_bfloat162*)(lo + i)     = __nv_bfloat162(l0, l1);
    *(__nv_bfloat162*)(lo + i + 2) = __nv_bfloat162(l2, l3);
}

// ---------------------------------------------------------------------------
// mma.sync NT GEMM, bf16x3 split (hh + hl + lh into one fp32 accumulator).
// Cm[m,n] = sum_k A[m,k]*B[n,k]. CTA: 128x128, 8 warps (2x4), warp: 64x32.
// K chunks of 32, 2-stage cp.async double buffer.
// SMEM per stage: 4 tiles (Ah, Al, Bh, Bl), each 128 rows x 40 bf16 (80 B).
// ---------------------------------------------------------------------------
#define TSTRIDE   80          // bytes per smem row (32 bf16 data + 8 pad)
#define TILE_B    (128 * TSTRIDE)       // 10240
#define STAGE_B   (4 * TILE_B)          // 40960
#define GEMM_SMEM (2 * STAGE_B)         // 81920

__global__ __launch_bounds__(256)
void gemm_mma(const __nv_bfloat16* __restrict__ Ah, const __nv_bfloat16* __restrict__ Al,
              const __nv_bfloat16* __restrict__ Bh, const __nv_bfloat16* __restrict__ Bl,
              float* __restrict__ Cm, int N, int K)
{
    extern __shared__ __align__(16) char smem[];
    const uint32_t sbase = smem_u32(smem);
    const int tid  = threadIdx.x;
    const int warp = tid >> 5, lane = tid & 31;
    const int wm = warp >> 2, wn = warp & 3;      // warp grid 2 x 4
    const int m0 = blockIdx.y * 128;
    const int n0 = blockIdx.x * 128;
    const int NKC = K >> 5;                       // 32 chunks of K=32

    float acc[4][4][4];
#pragma unroll
    for (int i = 0; i < 4; ++i)
#pragma unroll
        for (int j = 0; j < 4; ++j)
#pragma unroll
            for (int q = 0; q < 4; ++q) acc[i][j][q] = 0.f;

    // loader: tid -> rows (tid>>2) and (tid>>2)+64, 16B chunk tid&3
    const int lr = tid >> 2, lc = tid & 3;

    auto load_stage = [&](int stage, int kc) {
        const uint32_t stgb = sbase + stage * STAGE_B;
        const int kel = (kc << 5) + (lc << 3);     // element offset in K
#pragma unroll
        for (int tile = 0; tile < 4; ++tile) {
            const __nv_bfloat16* src =
                (tile == 0) ? Ah : (tile == 1) ? Al : (tile == 2) ? Bh : Bl;
            const int g0 = (tile < 2) ? m0 : n0;
            const uint32_t tb = stgb + tile * TILE_B;
            cp_async16(tb + lr * TSTRIDE + lc * 16,
                       src + (size_t)(g0 + lr) * K + kel);
            cp_async16(tb + (lr + 64) * TSTRIDE + lc * 16,
                       src + (size_t)(g0 + lr + 64) * K + kel);
        }
    };

    // ldmatrix per-thread address offsets (within a tile, bytes)
    const int a_row  = wm * 64 + (lane & 15);
    const int a_half = lane >> 4;
    const int bsub   = lane >> 3;
    const int b_rowi = ((bsub >> 1) << 3) + (lane & 7);
    const int b_half = bsub & 1;

    load_stage(0, 0);
    CP_COMMIT();

    for (int kc = 0; kc < NKC; ++kc) {
        if (kc + 1 < NKC) {
            load_stage((kc + 1) & 1, kc + 1);
            CP_COMMIT();
            CP_WAIT(1);
        } else {
            CP_WAIT(0);
        }
        __syncthreads();

        const uint32_t stgb = sbase + (kc & 1) * STAGE_B;
#pragma unroll
        for (int ks = 0; ks < 2; ++ks) {
            const int kb = ks * 32;                        // byte offset of k16
            uint32_t ah[4][4], al[4][4], bh[2][4], bl[2][4];
#pragma unroll
            for (int mi = 0; mi < 4; ++mi) {
                uint32_t off = (uint32_t)((a_row + mi * 16) * TSTRIDE
                                          + kb + a_half * 16);
                ldm_x4(ah[mi], stgb + off);
                ldm_x4(al[mi], stgb + TILE_B + off);
            }
#pragma unroll
            for (int p = 0; p < 2; ++p) {
                uint32_t off = (uint32_t)((wn * 32 + p * 16 + b_rowi) * TSTRIDE
                                          + kb + b_half * 16);
                ldm_x4(bh[p], stgb + 2 * TILE_B + off);
                ldm_x4(bl[p], stgb + 3 * TILE_B + off);
            }
#pragma unroll
            for (int mi = 0; mi < 4; ++mi)
#pragma unroll
                for (int ni = 0; ni < 4; ++ni) {
                    const uint32_t* bhp = &bh[ni >> 1][(ni & 1) * 2];
                    const uint32_t* blp = &bl[ni >> 1][(ni & 1) * 2];
                    mma16816(acc[mi][ni], ah[mi], bhp);
                    mma16816(acc[mi][ni], ah[mi], blp);
                    mma16816(acc[mi][ni], al[mi], bhp);
                }
        }
        __syncthreads();
    }

    // store: thread holds rows (lane>>2), (lane>>2)+8; cols 2*(lane&3), +1
#pragma unroll
    for (int mi = 0; mi < 4; ++mi) {
#pragma unroll
        for (int ni = 0; ni < 4; ++ni) {
            int row = m0 + wm * 64 + mi * 16 + (lane >> 2);
            int col = n0 + wn * 32 + ni * 8 + 2 * (lane & 3);
            *(float2*)(Cm + (size_t)row * N + col) =
                make_float2(acc[mi][ni][0], acc[mi][ni][1]);
            *(float2*)(Cm + (size_t)(row + 8) * N + col) =
                make_float2(acc[mi][ni][2], acc[mi][ni][3]);
        }
    }
}

// ---------------------------------------------------------------------------
// zero g_G
// ---------------------------------------------------------------------------
__global__ void zeroG_kernel() {
    int i = blockIdx.x * 256 + threadIdx.x;
    if (i < NB * SS * SS) g_G[i] = 0.f;
}

// ---------------------------------------------------------------------------
// Gram: grid (64 images, 4 k-splits), 12x12 thread grid of 3x3 register tiles
// ---------------------------------------------------------------------------
__global__ __launch_bounds__(256)
void gram_kernel(const float* __restrict__ img)
{
    const int b  = blockIdx.x;
    const int ks = blockIdx.y;            // K chunk of 256
    const int t  = threadIdx.x;
    __shared__ float sI[SS][257];

    for (int idx = t; idx < SS * 256; idx += 256) {
        int r = idx >> 8, k = idx & 255;
        sI[r][k] = img[(size_t)(b * SS + r) * DD + ks * 256 + k];
    }
    __syncthreads();

    if (t < 144) {
        const int ti = (t / 12) * 3, tj = (t % 12) * 3;
        float acc[3][3] = {{0,0,0},{0,0,0},{0,0,0}};
#pragma unroll 4
        for (int k = 0; k < 256; ++k) {
            float a0 = sI[ti][k],     a1 = sI[ti + 1][k], a2 = sI[ti + 2][k];
            float b0 = sI[tj][k],     b1 = sI[tj + 1][k], b2 = sI[tj + 2][k];
            acc[0][0] = fmaf(a0, b0, acc[0][0]); acc[0][1] = fmaf(a0, b1, acc[0][1]);
            acc[0][2] = fmaf(a0, b2, acc[0][2]);
            acc[1][0] = fmaf(a1, b0, acc[1][0]); acc[1][1] = fmaf(a1, b1, acc[1][1]);
            acc[1][2] = fmaf(a1, b2, acc[1][2]);
            acc[2][0] = fmaf(a2, b0, acc[2][0]); acc[2][1] = fmaf(a2, b1, acc[2][1]);
            acc[2][2] = fmaf(a2, b2, acc[2][2]);
        }
#pragma unroll
        for (int i = 0; i < 3; ++i)
#pragma unroll
            for (int j = 0; j < 3; ++j)
                atomicAdd(&g_G[b * SS * SS + (ti + i) * SS + tj + j], acc[i][j]);
    }
}

// ---------------------------------------------------------------------------
// Caption word norms
// ---------------------------------------------------------------------------
__global__ __launch_bounds__(256)
void w1_kernel(const float* __restrict__ cap)
{
    const int row  = blockIdx.x * 8 + (threadIdx.x >> 5);
    const int lane = threadIdx.x & 31;
    const float* p = cap + (size_t)row * DD;
    float s = 0.f;
    for (int k = lane; k < DD; k += 32) { float v = p[k]; s = fmaf(v, v, s); }
    s = wsum(s);
    if (lane == 0) g_w1[row] = sqrtf(s);
}

// ---------------------------------------------------------------------------
// Per-(image, caption) epilogue (unchanged from passing R2 kernel)
// ---------------------------------------------------------------------------
__global__ __launch_bounds__(256)
void pair_kernel(const int* __restrict__ cap_lens, float* __restrict__ out)
{
    const int i = blockIdx.x;    // caption
    const int b = blockIdx.y;    // image
    const int t = threadIdx.x;
    const int w = t >> 5, lane = t & 31;
    const int len = cap_lens[i];

    __shared__ float att[SS][33];
    __shared__ float cw[SS][33];
    __shared__ float aw[LMAXC][SS];
    __shared__ float sG[SS * SS];
    __shared__ float rs[LMAXC];

    for (int idx = t; idx < SS * SS; idx += 256) sG[idx] = g_G[b * SS * SS + idx];

    for (int s = w; s < SS; s += 8) {
        float v = g_A[(size_t)(b * SS + s) * NCAPR + i * LMAXC + lane];
        v = v > 0.f ? v : 0.1f * v;
        if (lane >= len) v = 0.f;
        float ssq = wsum(v * v);
        att[s][lane] = v / (sqrtf(ssq) + 1e-8f);
        cw[s][lane]  = g_C[(size_t)(b * SS + s) * NCAPR + i * LMAXC + lane];
    }
    __syncthreads();

    for (int l = w; l < LMAXC; l += 8) {
        float v0 = att[lane][l];
        float v1 = (lane < 4) ? att[32 + lane][l] : 0.f;
        float z0 = 9.0f * v0;
        float z1 = (lane < 4) ? 9.0f * v1 : -1e30f;
        float m  = wmax(fmaxf(z0, z1));
        float e0 = expf(z0 - m);
        float e1 = (lane < 4) ? expf(z1 - m) : 0.f;
        float inv = 1.0f / wsum(e0 + e1);
        aw[l][lane] = e0 * inv;
        if (lane < 4) aw[l][32 + lane] = e1 * inv;
    }
    __syncthreads();

    for (int l = w; l < LMAXC; l += 8) {
        float a0 = aw[l][lane];
        float a1 = (lane < 4) ? aw[l][32 + lane] : 0.f;
        float c0 = cw[lane][l];
        float c1 = (lane < 4) ? cw[32 + lane][l] : 0.f;
        float w12 = wsum(a0 * c0 + a1 * c1);

        float t0 = 0.f, t1 = 0.f;
#pragma unroll
        for (int s = 0; s < SS; ++s) {
            float av = aw[l][s];
            t0 = fmaf(av, sG[s * SS + lane], t0);
            if (lane < 4) t1 = fmaf(av, sG[s * SS + 32 + lane], t1);
        }
        float w2sq = wsum(t0 * a0 + t1 * a1);

        if (lane == 0) {
            float denom = fmaxf(g_w1[i * LMAXC + l] * sqrtf(fmaxf(w2sq, 0.f)), 1e-8f);
            rs[l] = w12 / denom;
        }
    }
    __syncthreads();

    if (w == 0) {
        float z = (lane < len) ? rs[lane] * 6.0f : -1e30f;
        float m = wmax(z);
        float e = (lane < len) ? expf(z - m) : 0.f;
        float ssum = wsum(e);
        if (lane == 0) out[b * NB + i] = (m + logf(ssum)) / 6.0f;
    }
}

// ---------------------------------------------------------------------------
extern "C" void kernel_launch(void* const* d_in, const int* in_sizes, int n_in,
                              void* d_out, int out_size)
{
    const float* images   = (const float*)d_in[0];
    const float* captions = (const float*)d_in[1];
    const int*   cap_lens = (const int*)  d_in[2];
    const float* W_g      = (const float*)d_in[3];
    float* out = (float*)d_out;

    float *pE, *pA, *pC;
    cudaGetSymbolAddress((void**)&pE, g_E);
    cudaGetSymbolAddress((void**)&pA, g_A);
    cudaGetSymbolAddress((void**)&pC, g_C);
    __nv_bfloat16 *iH, *iL, *cH, *cL, *wH, *wL, *eH, *eL;
    cudaGetSymbolAddress((void**)&iH, g_imgH); cudaGetSymbolAddress((void**)&iL, g_imgL);
    cudaGetSymbolAddress((void**)&cH, g_capH); cudaGetSymbolAddress((void**)&cL, g_capL);
    cudaGetSymbolAddress((void**)&wH, g_WH);   cudaGetSymbolAddress((void**)&wL, g_WL);
    cudaGetSymbolAddress((void**)&eH, g_EH);   cudaGetSymbolAddress((void**)&eL, g_EL);

    cudaFuncSetAttribute(gemm_mma, cudaFuncAttributeMaxDynamicSharedMemorySize, GEMM_SMEM);

    // bf16 hi/lo splits of all fp32 operands
    split_kernel<<<MROWS * DD / 1024, 256>>>(images,   iH, iL, MROWS * DD);
    split_kernel<<<NCAPR * DD / 1024, 256>>>(captions, cH, cL, NCAPR * DD);
    split_kernel<<<DD * DD / 1024,   256>>>(W_g,       wH, wL, DD * DD);

    // GEMM1: E = cap @ W^T  (2048 x 1024 x 1024)
    gemm_mma<<<dim3(DD / 128, NCAPR / 128), 256, GEMM_SMEM>>>(cH, cL, wH, wL, pE, DD, DD);
    split_kernel<<<NCAPR * DD / 1024, 256>>>(pE, eH, eL, NCAPR * DD);
    // GEMM2: A = img @ E^T  (2304 x 2048 x 1024)
    gemm_mma<<<dim3(NCAPR / 128, MROWS / 128), 256, GEMM_SMEM>>>(iH, iL, eH, eL, pA, NCAPR, DD);
    // GEMM3: C = img @ cap^T (2304 x 2048 x 1024)
    gemm_mma<<<dim3(NCAPR / 128, MROWS / 128), 256, GEMM_SMEM>>>(iH, iL, cH, cL, pC, NCAPR, DD);

    // Gram + norms + fused epilogue
    zeroG_kernel<<<(NB * SS * SS + 255) / 256, 256>>>();
    gram_kernel<<<dim3(NB, 4), 256>>>(images);
    w1_kernel<<<NCAPR / 8, 256>>>(captions);
    pair_kernel<<<dim3(NB, NB), 256>>>(cap_lens, out);
}

// round 12
// speedup vs baseline: 2.7529x; 1.2042x over previous
#include <cuda_runtime.h>
#include <cuda_bf16.h>
#include <math.h>
#include <stdint.h>

// Problem constants
#define DD     1024
#define NB     64
#define SS     36
#define LMAXC  32
#define MROWS  (NB * SS)      // 2304
#define NCAPR  (NB * LMAXC)   // 2048
#define KCH    16             // K chunks of 64 (DD/64)
#define TILE_BYTES 16384      // 128 rows x 64 bf16
#define TILE_ELEMS 8192

// ---------------------------------------------------------------------------
// Device scratch. Split operands live in a BLOCKED, PRE-SWIZZLED layout:
//   blob(rb, kc) = base + (rb*KCH + kc)*TILE_ELEMS, holding a 128x64 bf16
//   tile where element (r, k) sits at byte SWZ128(r*128 + k*2).
// ---------------------------------------------------------------------------
__device__ float g_A[MROWS * NCAPR];
__device__ float g_C[MROWS * NCAPR];
__device__ float g_G[NB * SS * SS];
__device__ float g_w1[NCAPR];
__device__ __nv_bfloat16 g_imgH[MROWS * DD], g_imgL[MROWS * DD];
__device__ __nv_bfloat16 g_capH[NCAPR * DD], g_capL[NCAPR * DD];
__device__ __nv_bfloat16 g_WH[DD * DD],     g_WL[DD * DD];
__device__ __nv_bfloat16 g_EH[NCAPR * DD],  g_EL[NCAPR * DD];

// ---------------------------------------------------------------------------
// helpers
// ---------------------------------------------------------------------------
__device__ __forceinline__ uint32_t smem_u32(const void* p) {
    uint32_t a;
    asm("{ .reg .u64 t; cvta.to.shared.u64 t, %1; cvt.u32.u64 %0, t; }" : "=r"(a) : "l"(p));
    return a;
}
__device__ __forceinline__ void mbar_init(uint32_t mbar, uint32_t cnt) {
    asm volatile("mbarrier.init.shared.b64 [%0], %1;" :: "r"(mbar), "r"(cnt) : "memory");
}
__device__ __forceinline__ void mbar_expect_tx(uint32_t mbar, uint32_t tx) {
    asm volatile("mbarrier.arrive.expect_tx.shared.b64 _, [%0], %1;"
                 :: "r"(mbar), "r"(tx) : "memory");
}
__device__ __forceinline__ void mbar_wait(uint32_t mbar, uint32_t parity) {
    asm volatile(
        "{\n\t.reg .pred P;\n"
        "WL_%=:\n\t"
        "mbarrier.try_wait.parity.acquire.cta.shared::cta.b64 P, [%0], %1, 0x989680;\n\t"
        "@P bra WD_%=;\n\t"
        "bra WL_%=;\n"
        "WD_%=:\n\t}"
        :: "r"(mbar), "r"(parity) : "memory");
}
__device__ __forceinline__ void bulk_g2s(uint32_t dst, const void* src,
                                         uint32_t bytes, uint32_t mbar) {
    asm volatile(
        "cp.async.bulk.shared::cluster.global.mbarrier::complete_tx::bytes "
        "[%0], [%1], %2, [%3];"
        :: "r"(dst), "l"(src), "r"(bytes), "r"(mbar) : "memory");
}
__device__ __forceinline__ void ldm_x4(uint32_t* r, uint32_t addr) {
    asm volatile("ldmatrix.sync.aligned.m8n8.x4.shared.b16 {%0,%1,%2,%3}, [%4];"
                 : "=r"(r[0]), "=r"(r[1]), "=r"(r[2]), "=r"(r[3]) : "r"(addr));
}
__device__ __forceinline__ void mma16816(float* d, const uint32_t* a,
                                         const uint32_t* b) {
    asm volatile(
        "mma.sync.aligned.m16n8k16.row.col.f32.bf16.bf16.f32 "
        "{%0,%1,%2,%3}, {%4,%5,%6,%7}, {%8,%9}, {%0,%1,%2,%3};"
        : "+f"(d[0]), "+f"(d[1]), "+f"(d[2]), "+f"(d[3])
        : "r"(a[0]), "r"(a[1]), "r"(a[2]), "r"(a[3]), "r"(b[0]), "r"(b[1]));
}
__device__ __forceinline__ float wsum(float v) {
#pragma unroll
    for (int o = 16; o > 0; o >>= 1) v += __shfl_xor_sync(0xffffffffu, v, o);
    return v;
}
__device__ __forceinline__ float wmax(float v) {
#pragma unroll
    for (int o = 16; o > 0; o >>= 1) v = fmaxf(v, __shfl_xor_sync(0xffffffffu, v, o));
    return v;
}

// ---------------------------------------------------------------------------
// split: fp32 row-major [nrows][1024] -> blocked swizzled bf16 hi/lo
// one thread handles 8 consecutive elements (one 16B output chunk)
// ---------------------------------------------------------------------------
__global__ __launch_bounds__(256)
void split_blocked(const float* __restrict__ x, __nv_bfloat16* __restrict__ H,
                   __nv_bfloat16* __restrict__ L, int nrows)
{
    int i8 = blockIdx.x * 256 + threadIdx.x;       // 16B-chunk id
    if (i8 >= nrows * (DD / 8)) return;
    int row = i8 >> 7;                             // 128 chunks per row
    int c8  = i8 & 127;
    int kc  = c8 >> 3, kk8 = c8 & 7;

    const float* src = x + (size_t)row * DD + c8 * 8;
    float4 v0 = *(const float4*)src;
    float4 v1 = *(const float4*)(src + 4);
    float v[8] = {v0.x, v0.y, v0.z, v0.w, v1.x, v1.y, v1.z, v1.w};

    __nv_bfloat16 h[8], l[8];
#pragma unroll
    for (int j = 0; j < 8; ++j) {
        h[j] = __float2bfloat16(v[j]);
        l[j] = __float2bfloat16(v[j] - __bfloat162float(h[j]));
    }
    int rb = row >> 7, r = row & 127;
    uint32_t boff = (uint32_t)r * 128 + (uint32_t)((kk8 ^ (r & 7)) * 16);
    size_t eoff = ((size_t)(rb * KCH + kc)) * TILE_ELEMS + (boff >> 1);
    *(uint4*)(H + eoff) = *(uint4*)h;
    *(uint4*)(L + eoff) = *(uint4*)l;
}

// ---------------------------------------------------------------------------
// bulk-load NT GEMM, bf16x3 split (hh + hl + lh). K = 1024 (16 chunks of 64).
// CTA 128x128, 8 warps (2x4), warp 64x32. Operands pre-blocked + pre-swizzled;
// each chunk = 4 x cp.async.bulk of 16KB. Output: fp32 row-major (Cout) or
// blocked-split bf16 (EH/EL, for the E = cap @ W^T intermediate).
// ---------------------------------------------------------------------------
#define STAGE_B   (4 * TILE_BYTES)      // 65536
#define GEMM_SMEM (1024 + 2 * STAGE_B)  // 132096

__global__ __launch_bounds__(256)
void gemm_bulk(const __nv_bfloat16* __restrict__ AH, const __nv_bfloat16* __restrict__ AL,
               const __nv_bfloat16* __restrict__ BH, const __nv_bfloat16* __restrict__ BL,
               float* __restrict__ Cout, __nv_bfloat16* __restrict__ EH,
               __nv_bfloat16* __restrict__ EL, int N)
{
    extern __shared__ __align__(1024) char smem[];
    const uint32_t sbase = smem_u32(smem);
    const uint32_t tile0 = (sbase + 1024 + 1023) & ~1023u;
    const int tid  = threadIdx.x;
    const int warp = tid >> 5, lane = tid & 31;
    const int wm = warp >> 2, wn = warp & 3;
    const int mb = blockIdx.y, nb = blockIdx.x;

    if (tid == 0) { mbar_init(sbase + 8, 1); mbar_init(sbase + 16, 1); }
    __syncthreads();

    auto issue = [&](int kc) {
        const int s = kc & 1;
        const uint32_t stg = tile0 + s * STAGE_B;
        const uint32_t mb_full = sbase + 8 + s * 8;
        mbar_expect_tx(mb_full, STAGE_B);
        const size_t aoff = ((size_t)(mb * KCH + kc)) * TILE_BYTES;
        const size_t boff = ((size_t)(nb * KCH + kc)) * TILE_BYTES;
        bulk_g2s(stg,                  (const char*)AH + aoff, TILE_BYTES, mb_full);
        bulk_g2s(stg + TILE_BYTES,     (const char*)AL + aoff, TILE_BYTES, mb_full);
        bulk_g2s(stg + 2 * TILE_BYTES, (const char*)BH + boff, TILE_BYTES, mb_full);
        bulk_g2s(stg + 3 * TILE_BYTES, (const char*)BL + boff, TILE_BYTES, mb_full);
    };
    if (tid == 0) issue(0);

    float acc[4][4][4];
#pragma unroll
    for (int i = 0; i < 4; ++i)
#pragma unroll
        for (int j = 0; j < 4; ++j)
#pragma unroll
            for (int q = 0; q < 4; ++q) acc[i][j][q] = 0.f;

    // fragment addressing (swizzled): addr(r, c16) = r*128 + (c16*16 ^ (r&7)*16)
    const int a_row  = wm * 64 + (lane & 15);
    const int a_half = lane >> 4;
    const int axor   = (a_row & 7) << 4;
    const int bsub   = lane >> 3;
    const int b_rowi = ((bsub >> 1) << 3) + (lane & 7);
    const int b_half = bsub & 1;
    const int bxor   = (lane & 7) << 4;

    for (int kc = 0; kc < KCH; ++kc) {
        if (tid == 0 && kc + 1 < KCH) issue(kc + 1);
        mbar_wait(sbase + 8 + (kc & 1) * 8, (kc >> 1) & 1);

        const uint32_t stg = tile0 + (kc & 1) * STAGE_B;
#pragma unroll
        for (int ks = 0; ks < 4; ++ks) {
            const int kb = ks * 32;                  // bytes per k16 step
            uint32_t ah[4][4], al[4][4], bh[2][4], bl[2][4];
#pragma unroll
            for (int mi = 0; mi < 4; ++mi) {
                uint32_t off = (uint32_t)((a_row + mi * 16) * 128
                                          + ((kb + a_half * 16) ^ axor));
                ldm_x4(ah[mi], stg + off);
                ldm_x4(al[mi], stg + TILE_BYTES + off);
            }
#pragma unroll
            for (int p = 0; p < 2; ++p) {
                uint32_t off = (uint32_t)((wn * 32 + p * 16 + b_rowi) * 128
                                          + ((kb + b_half * 16) ^ bxor));
                ldm_x4(bh[p], stg + 2 * TILE_BYTES + off);
                ldm_x4(bl[p], stg + 3 * TILE_BYTES + off);
            }
#pragma unroll
            for (int mi = 0; mi < 4; ++mi)
#pragma unroll
                for (int ni = 0; ni < 4; ++ni) {
                    const uint32_t* bhp = &bh[ni >> 1][(ni & 1) * 2];
                    const uint32_t* blp = &bl[ni >> 1][(ni & 1) * 2];
                    mma16816(acc[mi][ni], ah[mi], bhp);
                    mma16816(acc[mi][ni], ah[mi], blp);
                    mma16816(acc[mi][ni], al[mi], bhp);
                }
        }
        __syncthreads();
    }

    if (Cout) {
#pragma unroll
        for (int mi = 0; mi < 4; ++mi)
#pragma unroll
            for (int ni = 0; ni < 4; ++ni) {
                int row = mb * 128 + wm * 64 + mi * 16 + (lane >> 2);
                int col = nb * 128 + wn * 32 + ni * 8 + 2 * (lane & 3);
                *(float2*)(Cout + (size_t)row * N + col) =
                    make_float2(acc[mi][ni][0], acc[mi][ni][1]);
                *(float2*)(Cout + (size_t)(row + 8) * N + col) =
                    make_float2(acc[mi][ni][2], acc[mi][ni][3]);
            }
    } else {
        // split output straight into blocked layout (rows = this GEMM's M dim,
        // k = this GEMM's N dim), for use as a B operand downstream.
#pragma unroll
        for (int mi = 0; mi < 4; ++mi)
#pragma unroll
            for (int ni = 0; ni < 4; ++ni)
#pragma unroll
                for (int half = 0; half < 2; ++half) {
                    int r = wm * 64 + mi * 16 + (lane >> 2) + half * 8;
                    int cc = wn * 32 + ni * 8 + 2 * (lane & 3);
                    int kcD = nb * 2 + (cc >> 6);
                    int kk = cc & 63;
                    float v0 = acc[mi][ni][half * 2];
                    float v1 = acc[mi][ni][half * 2 + 1];
                    __nv_bfloat16 h0 = __float2bfloat16(v0);
                    __nv_bfloat16 h1 = __float2bfloat16(v1);
                    __nv_bfloat16 l0 = __float2bfloat16(v0 - __bfloat162float(h0));
                    __nv_bfloat16 l1 = __float2bfloat16(v1 - __bfloat162float(h1));
                    uint32_t boff = (uint32_t)r * 128
                                    + (uint32_t)((kk * 2) ^ ((r & 7) << 4));
                    size_t eoff = ((size_t)(mb * KCH + kcD)) * TILE_ELEMS + (boff >> 1);
                    *(__nv_bfloat162*)(EH + eoff) = __nv_bfloat162(h0, h1);
                    *(__nv_bfloat162*)(EL + eoff) = __nv_bfloat162(l0, l1);
                }
    }
}

// ---------------------------------------------------------------------------
__global__ void zeroG_kernel() {
    int i = blockIdx.x * 256 + threadIdx.x;
    if (i < NB * SS * SS) g_G[i] = 0.f;
}

// Gram: grid (64 images, 4 k-splits), 3x3 register tiles on 12x12 threads
__global__ __launch_bounds__(256)
void gram_kernel(const float* __restrict__ img)
{
    const int b  = blockIdx.x;
    const int ks = blockIdx.y;
    const int t  = threadIdx.x;
    __shared__ float sI[SS][257];

    for (int idx = t; idx < SS * 256; idx += 256) {
        int r = idx >> 8, k = idx & 255;
        sI[r][k] = img[(size_t)(b * SS + r) * DD + ks * 256 + k];
    }
    __syncthreads();

    if (t < 144) {
        const int ti = (t / 12) * 3, tj = (t % 12) * 3;
        float acc[3][3] = {{0,0,0},{0,0,0},{0,0,0}};
#pragma unroll 4
        for (int k = 0; k < 256; ++k) {
            float a0 = sI[ti][k],     a1 = sI[ti + 1][k], a2 = sI[ti + 2][k];
            float b0 = sI[tj][k],     b1 = sI[tj + 1][k], b2 = sI[tj + 2][k];
            acc[0][0] = fmaf(a0, b0, acc[0][0]); acc[0][1] = fmaf(a0, b1, acc[0][1]);
            acc[0][2] = fmaf(a0, b2, acc[0][2]);
            acc[1][0] = fmaf(a1, b0, acc[1][0]); acc[1][1] = fmaf(a1, b1, acc[1][1]);
            acc[1][2] = fmaf(a1, b2, acc[1][2]);
            acc[2][0] = fmaf(a2, b0, acc[2][0]); acc[2][1] = fmaf(a2, b1, acc[2][1]);
            acc[2][2] = fmaf(a2, b2, acc[2][2]);
        }
#pragma unroll
        for (int i = 0; i < 3; ++i)
#pragma unroll
            for (int j = 0; j < 3; ++j)
                atomicAdd(&g_G[b * SS * SS + (ti + i) * SS + tj + j], acc[i][j]);
    }
}

__global__ __launch_bounds__(256)
void w1_kernel(const float* __restrict__ cap)
{
    const int row  = blockIdx.x * 8 + (threadIdx.x >> 5);
    const int lane = threadIdx.x & 31;
    const float* p = cap + (size_t)row * DD;
    float s = 0.f;
    for (int k = lane; k < DD; k += 32) { float v = p[k]; s = fmaf(v, v, s); }
    s = wsum(s);
    if (lane == 0) g_w1[row] = sqrtf(s);
}

// Per-(image, caption) epilogue (unchanged, hardware-validated)
__global__ __launch_bounds__(256)
void pair_kernel(const int* __restrict__ cap_lens, float* __restrict__ out)
{
    const int i = blockIdx.x;
    const int b = blockIdx.y;
    const int t = threadIdx.x;
    const int w = t >> 5, lane = t & 31;
    const int len = cap_lens[i];

    __shared__ float att[SS][33];
    __shared__ float cw[SS][33];
    __shared__ float aw[LMAXC][SS];
    __shared__ float sG[SS * SS];
    __shared__ float rs[LMAXC];

    for (int idx = t; idx < SS * SS; idx += 256) sG[idx] = g_G[b * SS * SS + idx];

    for (int s = w; s < SS; s += 8) {
        float v = g_A[(size_t)(b * SS + s) * NCAPR + i * LMAXC + lane];
        v = v > 0.f ? v : 0.1f * v;
        if (lane >= len) v = 0.f;
        float ssq = wsum(v * v);
        att[s][lane] = v / (sqrtf(ssq) + 1e-8f);
        cw[s][lane]  = g_C[(size_t)(b * SS + s) * NCAPR + i * LMAXC + lane];
    }
    __syncthreads();

    for (int l = w; l < LMAXC; l += 8) {
        float v0 = att[lane][l];
        float v1 = (lane < 4) ? att[32 + lane][l] : 0.f;
        float z0 = 9.0f * v0;
        float z1 = (lane < 4) ? 9.0f * v1 : -1e30f;
        float m  = wmax(fmaxf(z0, z1));
        float e0 = expf(z0 - m);
        float e1 = (lane < 4) ? expf(z1 - m) : 0.f;
        float inv = 1.0f / wsum(e0 + e1);
        aw[l][lane] = e0 * inv;
        if (lane < 4) aw[l][32 + lane] = e1 * inv;
    }
    __syncthreads();

    for (int l = w; l < LMAXC; l += 8) {
        float a0 = aw[l][lane];
        float a1 = (lane < 4) ? aw[l][32 + lane] : 0.f;
        float c0 = cw[lane][l];
        float c1 = (lane < 4) ? cw[32 + lane][l] : 0.f;
        float w12 = wsum(a0 * c0 + a1 * c1);

        float t0 = 0.f, t1 = 0.f;
#pragma unroll
        for (int s = 0; s < SS; ++s) {
            float av = aw[l][s];
            t0 = fmaf(av, sG[s * SS + lane], t0);
            if (lane < 4) t1 = fmaf(av, sG[s * SS + 32 + lane], t1);
        }
        float w2sq = wsum(t0 * a0 + t1 * a1);

        if (lane == 0) {
            float denom = fmaxf(g_w1[i * LMAXC + l] * sqrtf(fmaxf(w2sq, 0.f)), 1e-8f);
            rs[l] = w12 / denom;
        }
    }
    __syncthreads();

    if (w == 0) {
        float z = (lane < len) ? rs[lane] * 6.0f : -1e30f;
        float m = wmax(z);
        float e = (lane < len) ? expf(z - m) : 0.f;
        float ssum = wsum(e);
        if (lane == 0) out[b * NB + i] = (m + logf(ssum)) / 6.0f;
    }
}

// ---------------------------------------------------------------------------
extern "C" void kernel_launch(void* const* d_in, const int* in_sizes, int n_in,
                              void* d_out, int out_size)
{
    const float* images   = (const float*)d_in[0];
    const float* captions = (const float*)d_in[1];
    const int*   cap_lens = (const int*)  d_in[2];
    const float* W_g      = (const float*)d_in[3];
    float* out = (float*)d_out;

    float *pA, *pC;
    cudaGetSymbolAddress((void**)&pA, g_A);
    cudaGetSymbolAddress((void**)&pC, g_C);
    __nv_bfloat16 *iH, *iL, *cH, *cL, *wH, *wL, *eH, *eL;
    cudaGetSymbolAddress((void**)&iH, g_imgH); cudaGetSymbolAddress((void**)&iL, g_imgL);
    cudaGetSymbolAddress((void**)&cH, g_capH); cudaGetSymbolAddress((void**)&cL, g_capL);
    cudaGetSymbolAddress((void**)&wH, g_WH);   cudaGetSymbolAddress((void**)&wL, g_WL);
    cudaGetSymbolAddress((void**)&eH, g_EH);   cudaGetSymbolAddress((void**)&eL, g_EL);

    cudaFuncSetAttribute(gemm_bulk, cudaFuncAttributeMaxDynamicSharedMemorySize, GEMM_SMEM);

    // blocked + swizzled bf16 hi/lo splits of inputs
    split_blocked<<<MROWS * (DD / 8) / 256, 256>>>(images,   iH, iL, MROWS);
    split_blocked<<<NCAPR * (DD / 8) / 256, 256>>>(captions, cH, cL, NCAPR);
    split_blocked<<<DD * (DD / 8) / 256,    256>>>(W_g,      wH, wL, DD);

    // GEMM1: E = cap @ W^T -> blocked-split EH/EL directly
    gemm_bulk<<<dim3(DD / 128, NCAPR / 128), 256, GEMM_SMEM>>>(
        cH, cL, wH, wL, nullptr, eH, eL, DD);
    // GEMM2: A = img @ E^T  (fp32 out)
    gemm_bulk<<<dim3(NCAPR / 128, MROWS / 128), 256, GEMM_SMEM>>>(
        iH, iL, eH, eL, pA, nullptr, nullptr, NCAPR);
    // GEMM3: C = img @ cap^T (fp32 out)
    gemm_bulk<<<dim3(NCAPR / 128, MROWS / 128), 256, GEMM_SMEM>>>(
        iH, iL, cH, cL, pC, nullptr, nullptr, NCAPR);

    // Gram + norms + fused epilogue
    zeroG_kernel<<<(NB * SS * SS + 255) / 256, 256>>>();
    gram_kernel<<<dim3(NB, 4), 256>>>(images);
    w1_kernel<<<NCAPR / 8, 256>>>(captions);
    pair_kernel<<<dim3(NB, NB), 256>>>(cap_lens, out);
}

// round 16
// speedup vs baseline: 2.8029x; 1.0181x over previous
#include <cuda_runtime.h>
#include <cuda_bf16.h>
#include <math.h>
#include <stdint.h>

// Problem constants
#define DD     1024
#define NB     64
#define SS     36
#define LMAXC  32
#define MROWS  (NB * SS)      // 2304
#define NCAPR  (NB * LMAXC)   // 2048
#define KCH    16             // K chunks of 64 (DD/64)
#define TILE_BYTES 16384      // 128 rows x 64 bf16
#define TILE_ELEMS 8192

// ---------------------------------------------------------------------------
// Device scratch. Split operands live in a BLOCKED, PRE-SWIZZLED layout:
//   blob(rb, kc) = base + (rb*KCH + kc)*TILE_ELEMS, holding a 128x64 bf16
//   tile where element (r, k) sits at byte SWZ128(r*128 + k*2).
// ---------------------------------------------------------------------------
__device__ float g_A[MROWS * NCAPR];
__device__ float g_C[MROWS * NCAPR];
__device__ float g_G[NB * SS * SS];
__device__ float g_w1[NCAPR];
__device__ __nv_bfloat16 g_imgH[MROWS * DD], g_imgL[MROWS * DD];
__device__ __nv_bfloat16 g_capH[NCAPR * DD], g_capL[NCAPR * DD];
__device__ __nv_bfloat16 g_WH[DD * DD],     g_WL[DD * DD];
__device__ __nv_bfloat16 g_EH[NCAPR * DD],  g_EL[NCAPR * DD];

// ---------------------------------------------------------------------------
// helpers
// ---------------------------------------------------------------------------
__device__ __forceinline__ uint32_t smem_u32(const void* p) {
    uint32_t a;
    asm("{ .reg .u64 t; cvta.to.shared.u64 t, %1; cvt.u32.u64 %0, t; }" : "=r"(a) : "l"(p));
    return a;
}
__device__ __forceinline__ void mbar_init(uint32_t mbar, uint32_t cnt) {
    asm volatile("mbarrier.init.shared.b64 [%0], %1;" :: "r"(mbar), "r"(cnt) : "memory");
}
__device__ __forceinline__ void mbar_expect_tx(uint32_t mbar, uint32_t tx) {
    asm volatile("mbarrier.arrive.expect_tx.shared.b64 _, [%0], %1;"
                 :: "r"(mbar), "r"(tx) : "memory");
}
__device__ __forceinline__ void mbar_wait(uint32_t mbar, uint32_t parity) {
    asm volatile(
        "{\n\t.reg .pred P;\n"
        "WL_%=:\n\t"
        "mbarrier.try_wait.parity.acquire.cta.shared::cta.b64 P, [%0], %1, 0x989680;\n\t"
        "@P bra WD_%=;\n\t"
        "bra WL_%=;\n"
        "WD_%=:\n\t}"
        :: "r"(mbar), "r"(parity) : "memory");
}
__device__ __forceinline__ void bulk_g2s(uint32_t dst, const void* src,
                                         uint32_t bytes, uint32_t mbar) {
    asm volatile(
        "cp.async.bulk.shared::cluster.global.mbarrier::complete_tx::bytes "
        "[%0], [%1], %2, [%3];"
        :: "r"(dst), "l"(src), "r"(bytes), "r"(mbar) : "memory");
}
__device__ __forceinline__ void ldm_x4(uint32_t* r, uint32_t addr) {
    asm volatile("ldmatrix.sync.aligned.m8n8.x4.shared.b16 {%0,%1,%2,%3}, [%4];"
                 : "=r"(r[0]), "=r"(r[1]), "=r"(r[2]), "=r"(r[3]) : "r"(addr));
}
__device__ __forceinline__ void mma16816(float* d, const uint32_t* a,
                                         const uint32_t* b) {
    asm volatile(
        "mma.sync.aligned.m16n8k16.row.col.f32.bf16.bf16.f32 "
        "{%0,%1,%2,%3}, {%4,%5,%6,%7}, {%8,%9}, {%0,%1,%2,%3};"
        : "+f"(d[0]), "+f"(d[1]), "+f"(d[2]), "+f"(d[3])
        : "r"(a[0]), "r"(a[1]), "r"(a[2]), "r"(a[3]), "r"(b[0]), "r"(b[1]));
}
__device__ __forceinline__ float wsum(float v) {
#pragma unroll
    for (int o = 16; o > 0; o >>= 1) v += __shfl_xor_sync(0xffffffffu, v, o);
    return v;
}
__device__ __forceinline__ float wmax(float v) {
#pragma unroll
    for (int o = 16; o > 0; o >>= 1) v = fmaxf(v, __shfl_xor_sync(0xffffffffu, v, o));
    return v;
}

// ---------------------------------------------------------------------------
// split: fp32 row-major [nrows][1024] -> blocked swizzled bf16 hi/lo
// ---------------------------------------------------------------------------
__global__ __launch_bounds__(256)
void split_blocked(const float* __restrict__ x, __nv_bfloat16* __restrict__ H,
                   __nv_bfloat16* __restrict__ L, int nrows)
{
    int i8 = blockIdx.x * 256 + threadIdx.x;       // 16B-chunk id
    if (i8 >= nrows * (DD / 8)) return;
    int row = i8 >> 7;                             // 128 chunks per row
    int c8  = i8 & 127;
    int kc  = c8 >> 3, kk8 = c8 & 7;

    const float* src = x + (size_t)row * DD + c8 * 8;
    float4 v0 = *(const float4*)src;
    float4 v1 = *(const float4*)(src + 4);
    float v[8] = {v0.x, v0.y, v0.z, v0.w, v1.x, v1.y, v1.z, v1.w};

    __nv_bfloat16 h[8], l[8];
#pragma unroll
    for (int j = 0; j < 8; ++j) {
        h[j] = __float2bfloat16(v[j]);
        l[j] = __float2bfloat16(v[j] - __bfloat162float(h[j]));
    }
    int rb = row >> 7, r = row & 127;
    uint32_t boff = (uint32_t)r * 128 + (uint32_t)((kk8 ^ (r & 7)) * 16);
    size_t eoff = ((size_t)(rb * KCH + kc)) * TILE_ELEMS + (boff >> 1);
    *(uint4*)(H + eoff) = *(uint4*)h;
    *(uint4*)(L + eoff) = *(uint4*)l;
}

// ---------------------------------------------------------------------------
// GEMM1 kernel (unchanged, hardware-validated R12): bulk-load NT GEMM with
// bf16x3 split, writing blocked-split EH/EL directly from accumulators.
// ---------------------------------------------------------------------------
#define STAGE_B   (4 * TILE_BYTES)      // 65536
#define GEMM_SMEM (1024 + 2 * STAGE_B)  // 132096

__global__ __launch_bounds__(256)
void gemm_bulk(const __nv_bfloat16* __restrict__ AH, const __nv_bfloat16* __restrict__ AL,
               const __nv_bfloat16* __restrict__ BH, const __nv_bfloat16* __restrict__ BL,
               float* __restrict__ Cout, __nv_bfloat16* __restrict__ EH,
               __nv_bfloat16* __restrict__ EL, int N)
{
    extern __shared__ __align__(1024) char smem[];
    const uint32_t sbase = smem_u32(smem);
    const uint32_t tile0 = (sbase + 1024 + 1023) & ~1023u;
    const int tid  = threadIdx.x;
    const int warp = tid >> 5, lane = tid & 31;
    const int wm = warp >> 2, wn = warp & 3;
    const int mb = blockIdx.y, nb = blockIdx.x;

    if (tid == 0) { mbar_init(sbase + 8, 1); mbar_init(sbase + 16, 1); }
    __syncthreads();

    auto issue = [&](int kc) {
        const int s = kc & 1;
        const uint32_t stg = tile0 + s * STAGE_B;
        const uint32_t mb_full = sbase + 8 + s * 8;
        mbar_expect_tx(mb_full, STAGE_B);
        const size_t aoff = ((size_t)(mb * KCH + kc)) * TILE_BYTES;
        const size_t boff = ((size_t)(nb * KCH + kc)) * TILE_BYTES;
        bulk_g2s(stg,                  (const char*)AH + aoff, TILE_BYTES, mb_full);
        bulk_g2s(stg + TILE_BYTES,     (const char*)AL + aoff, TILE_BYTES, mb_full);
        bulk_g2s(stg + 2 * TILE_BYTES, (const char*)BH + boff, TILE_BYTES, mb_full);
        bulk_g2s(stg + 3 * TILE_BYTES, (const char*)BL + boff, TILE_BYTES, mb_full);
    };
    if (tid == 0) issue(0);

    float acc[4][4][4];
#pragma unroll
    for (int i = 0; i < 4; ++i)
#pragma unroll
        for (int j = 0; j < 4; ++j)
#pragma unroll
            for (int q = 0; q < 4; ++q) acc[i][j][q] = 0.f;

    const int a_row  = wm * 64 + (lane & 15);
    const int a_half = lane >> 4;
    const int axor   = (a_row & 7) << 4;
    const int bsub   = lane >> 3;
    const int b_rowi = ((bsub >> 1) << 3) + (lane & 7);
    const int b_half = bsub & 1;
    const int bxor   = (lane & 7) << 4;

    for (int kc = 0; kc < KCH; ++kc) {
        if (tid == 0 && kc + 1 < KCH) issue(kc + 1);
        mbar_wait(sbase + 8 + (kc & 1) * 8, (kc >> 1) & 1);

        const uint32_t stg = tile0 + (kc & 1) * STAGE_B;
#pragma unroll
        for (int ks = 0; ks < 4; ++ks) {
            const int kb = ks * 32;
            uint32_t ah[4][4], al[4][4], bh[2][4], bl[2][4];
#pragma unroll
            for (int mi = 0; mi < 4; ++mi) {
                uint32_t off = (uint32_t)((a_row + mi * 16) * 128
                                          + ((kb + a_half * 16) ^ axor));
                ldm_x4(ah[mi], stg + off);
                ldm_x4(al[mi], stg + TILE_BYTES + off);
            }
#pragma unroll
            for (int p = 0; p < 2; ++p) {
                uint32_t off = (uint32_t)((wn * 32 + p * 16 + b_rowi) * 128
                                          + ((kb + b_half * 16) ^ bxor));
                ldm_x4(bh[p], stg + 2 * TILE_BYTES + off);
                ldm_x4(bl[p], stg + 3 * TILE_BYTES + off);
            }
#pragma unroll
            for (int mi = 0; mi < 4; ++mi)
#pragma unroll
                for (int ni = 0; ni < 4; ++ni) {
                    const uint32_t* bhp = &bh[ni >> 1][(ni & 1) * 2];
                    const uint32_t* blp = &bl[ni >> 1][(ni & 1) * 2];
                    mma16816(acc[mi][ni], ah[mi], bhp);
                    mma16816(acc[mi][ni], ah[mi], blp);
                    mma16816(acc[mi][ni], al[mi], bhp);
                }
        }
        __syncthreads();
    }

    if (Cout) {
#pragma unroll
        for (int mi = 0; mi < 4; ++mi)
#pragma unroll
            for (int ni = 0; ni < 4; ++ni) {
                int row = mb * 128 + wm * 64 + mi * 16 + (lane >> 2);
                int col = nb * 128 + wn * 32 + ni * 8 + 2 * (lane & 3);
                *(float2*)(Cout + (size_t)row * N + col) =
                    make_float2(acc[mi][ni][0], acc[mi][ni][1]);
                *(float2*)(Cout + (size_t)(row + 8) * N + col) =
                    make_float2(acc[mi][ni][2], acc[mi][ni][3]);
            }
    } else {
#pragma unroll
        for (int mi = 0; mi < 4; ++mi)
#pragma unroll
            for (int ni = 0; ni < 4; ++ni)
#pragma unroll
                for (int half = 0; half < 2; ++half) {
                    int r = wm * 64 + mi * 16 + (lane >> 2) + half * 8;
                    int cc = wn * 32 + ni * 8 + 2 * (lane & 3);
                    int kcD = nb * 2 + (cc >> 6);
                    int kk = cc & 63;
                    float v0 = acc[mi][ni][half * 2];
                    float v1 = acc[mi][ni][half * 2 + 1];
                    __nv_bfloat16 h0 = __float2bfloat16(v0);
                    __nv_bfloat16 h1 = __float2bfloat16(v1);
                    __nv_bfloat16 l0 = __float2bfloat16(v0 - __bfloat162float(h0));
                    __nv_bfloat16 l1 = __float2bfloat16(v1 - __bfloat162float(h1));
                    uint32_t boff = (uint32_t)r * 128
                                    + (uint32_t)((kk * 2) ^ ((r & 7) << 4));
                    size_t eoff = ((size_t)(mb * KCH + kcD)) * TILE_ELEMS + (boff >> 1);
                    *(__nv_bfloat162*)(EH + eoff) = __nv_bfloat162(h0, h1);
                    *(__nv_bfloat162*)(EL + eoff) = __nv_bfloat162(l0, l1);
                }
    }
}

// ---------------------------------------------------------------------------
// gemm_dual: fused GEMM2+GEMM3. Shares the A (img) tile loads; computes
// O1 = img @ E^T and O2 = img @ cap^T in one pass. 6 tiles per stage
// (Ah, Al, B1h, B1l, B2h, B2l), 2 stages. Same proven pipeline schedule.
// ---------------------------------------------------------------------------
#define STAGE2_B   (6 * TILE_BYTES)       // 98304
#define GEMM2_SMEM (1024 + 2 * STAGE2_B)  // 197632

__global__ __launch_bounds__(256, 1)
void gemm_dual(const __nv_bfloat16* __restrict__ AH, const __nv_bfloat16* __restrict__ AL,
               const __nv_bfloat16* __restrict__ B1H, const __nv_bfloat16* __restrict__ B1L,
               const __nv_bfloat16* __restrict__ B2H, const __nv_bfloat16* __restrict__ B2L,
               float* __restrict__ O1, float* __restrict__ O2, int N)
{
    extern __shared__ __align__(1024) char smem[];
    const uint32_t sbase = smem_u32(smem);
    const uint32_t tile0 = (sbase + 1024 + 1023) & ~1023u;
    const int tid  = threadIdx.x;
    const int warp = tid >> 5, lane = tid & 31;
    const int wm = warp >> 2, wn = warp & 3;
    const int mb = blockIdx.y, nb = blockIdx.x;

    if (tid == 0) { mbar_init(sbase + 8, 1); mbar_init(sbase + 16, 1); }
    __syncthreads();

    auto issue = [&](int kc) {
        const int s = kc & 1;
        const uint32_t stg = tile0 + s * STAGE2_B;
        const uint32_t mb_full = sbase + 8 + s * 8;
        mbar_expect_tx(mb_full, STAGE2_B);
        const size_t aoff = ((size_t)(mb * KCH + kc)) * TILE_BYTES;
        const size_t boff = ((size_t)(nb * KCH + kc)) * TILE_BYTES;
        bulk_g2s(stg,                  (const char*)AH  + aoff, TILE_BYTES, mb_full);
        bulk_g2s(stg + TILE_BYTES,     (const char*)AL  + aoff, TILE_BYTES, mb_full);
        bulk_g2s(stg + 2 * TILE_BYTES, (const char*)B1H + boff, TILE_BYTES, mb_full);
        bulk_g2s(stg + 3 * TILE_BYTES, (const char*)B1L + boff, TILE_BYTES, mb_full);
        bulk_g2s(stg + 4 * TILE_BYTES, (const char*)B2H + boff, TILE_BYTES, mb_full);
        bulk_g2s(stg + 5 * TILE_BYTES, (const char*)B2L + boff, TILE_BYTES, mb_full);
    };
    if (tid == 0) issue(0);

    float acc1[4][4][4], acc2[4][4][4];
#pragma unroll
    for (int i = 0; i < 4; ++i)
#pragma unroll
        for (int j = 0; j < 4; ++j)
#pragma unroll
            for (int q = 0; q < 4; ++q) { acc1[i][j][q] = 0.f; acc2[i][j][q] = 0.f; }

    const int a_row  = wm * 64 + (lane & 15);
    const int a_half = lane >> 4;
    const int axor   = (a_row & 7) << 4;
    const int bsub   = lane >> 3;
    const int b_rowi = ((bsub >> 1) << 3) + (lane & 7);
    const int b_half = bsub & 1;
    const int bxor   = (lane & 7) << 4;

    for (int kc = 0; kc < KCH; ++kc) {
        if (tid == 0 && kc + 1 < KCH) issue(kc + 1);
        mbar_wait(sbase + 8 + (kc & 1) * 8, (kc >> 1) & 1);

        const uint32_t stg = tile0 + (kc & 1) * STAGE2_B;
#pragma unroll
        for (int ks = 0; ks < 4; ++ks) {
            const int kb = ks * 32;
            uint32_t ah[4][4], al[4][4];
            uint32_t b1h[2][4], b1l[2][4], b2h[2][4], b2l[2][4];
#pragma unroll
            for (int mi = 0; mi < 4; ++mi) {
                uint32_t off = (uint32_t)((a_row + mi * 16) * 128
                                          + ((kb + a_half * 16) ^ axor));
                ldm_x4(ah[mi], stg + off);
                ldm_x4(al[mi], stg + TILE_BYTES + off);
            }
#pragma unroll
            for (int p = 0; p < 2; ++p) {
                uint32_t off = (uint32_t)((wn * 32 + p * 16 + b_rowi) * 128
                                          + ((kb + b_half * 16) ^ bxor));
                ldm_x4(b1h[p], stg + 2 * TILE_BYTES + off);
                ldm_x4(b1l[p], stg + 3 * TILE_BYTES + off);
                ldm_x4(b2h[p], stg + 4 * TILE_BYTES + off);
                ldm_x4(b2l[p], stg + 5 * TILE_BYTES + off);
            }
#pragma unroll
            for (int mi = 0; mi < 4; ++mi)
#pragma unroll
                for (int ni = 0; ni < 4; ++ni) {
                    const uint32_t* p1h = &b1h[ni >> 1][(ni & 1) * 2];
                    const uint32_t* p1l = &b1l[ni >> 1][(ni & 1) * 2];
                    const uint32_t* p2h = &b2h[ni >> 1][(ni & 1) * 2];
                    const uint32_t* p2l = &b2l[ni >> 1][(ni & 1) * 2];
                    mma16816(acc1[mi][ni], ah[mi], p1h);
                    mma16816(acc1[mi][ni], ah[mi], p1l);
                    mma16816(acc1[mi][ni], al[mi], p1h);
                    mma16816(acc2[mi][ni], ah[mi], p2h);
                    mma16816(acc2[mi][ni], ah[mi], p2l);
                    mma16816(acc2[mi][ni], al[mi], p2h);
                }
        }
        __syncthreads();
    }

#pragma unroll
    for (int mi = 0; mi < 4; ++mi)
#pragma unroll
        for (int ni = 0; ni < 4; ++ni) {
            int row = mb * 128 + wm * 64 + mi * 16 + (lane >> 2);
            int col = nb * 128 + wn * 32 + ni * 8 + 2 * (lane & 3);
            *(float2*)(O1 + (size_t)row * N + col) =
                make_float2(acc1[mi][ni][0], acc1[mi][ni][1]);
            *(float2*)(O1 + (size_t)(row + 8) * N + col) =
                make_float2(acc1[mi][ni][2], acc1[mi][ni][3]);
            *(float2*)(O2 + (size_t)row * N + col) =
                make_float2(acc2[mi][ni][0], acc2[mi][ni][1]);
            *(float2*)(O2 + (size_t)(row + 8) * N + col) =
                make_float2(acc2[mi][ni][2], acc2[mi][ni][3]);
        }
}

// ---------------------------------------------------------------------------
__global__ void zeroG_kernel() {
    int i = blockIdx.x * 256 + threadIdx.x;
    if (i < NB * SS * SS) g_G[i] = 0.f;
}

// Gram: grid (64 images, 4 k-splits), 3x3 register tiles on 12x12 threads
__global__ __launch_bounds__(256)
void gram_kernel(const float* __restrict__ img)
{
    const int b  = blockIdx.x;
    const int ks = blockIdx.y;
    const int t  = threadIdx.x;
    __shared__ float sI[SS][257];

    for (int idx = t; idx < SS * 256; idx += 256) {
        int r = idx >> 8, k = idx & 255;
        sI[r][k] = img[(size_t)(b * SS + r) * DD + ks * 256 + k];
    }
    __syncthreads();

    if (t < 144) {
        const int ti = (t / 12) * 3, tj = (t % 12) * 3;
        float acc[3][3] = {{0,0,0},{0,0,0},{0,0,0}};
#pragma unroll 4
        for (int k = 0; k < 256; ++k) {
            float a0 = sI[ti][k],     a1 = sI[ti + 1][k], a2 = sI[ti + 2][k];
            float b0 = sI[tj][k],     b1 = sI[tj + 1][k], b2 = sI[tj + 2][k];
            acc[0][0] = fmaf(a0, b0, acc[0][0]); acc[0][1] = fmaf(a0, b1, acc[0][1]);
            acc[0][2] = fmaf(a0, b2, acc[0][2]);
            acc[1][0] = fmaf(a1, b0, acc[1][0]); acc[1][1] = fmaf(a1, b1, acc[1][1]);
            acc[1][2] = fmaf(a1, b2, acc[1][2]);
            acc[2][0] = fmaf(a2, b0, acc[2][0]); acc[2][1] = fmaf(a2, b1, acc[2][1]);
            acc[2][2] = fmaf(a2, b2, acc[2][2]);
        }
#pragma unroll
        for (int i = 0; i < 3; ++i)
#pragma unroll
            for (int j = 0; j < 3; ++j)
                atomicAdd(&g_G[b * SS * SS + (ti + i) * SS + tj + j], acc[i][j]);
    }
}

__global__ __launch_bounds__(256)
void w1_kernel(const float* __restrict__ cap)
{
    const int row  = blockIdx.x * 8 + (threadIdx.x >> 5);
    const int lane = threadIdx.x & 31;
    const float* p = cap + (size_t)row * DD;
    float s = 0.f;
    for (int k = lane; k < DD; k += 32) { float v = p[k]; s = fmaf(v, v, s); }
    s = wsum(s);
    if (lane == 0) g_w1[row] = sqrtf(s);
}

// Per-(image, caption) epilogue (unchanged, hardware-validated)
__global__ __launch_bounds__(256)
void pair_kernel(const int* __restrict__ cap_lens, float* __restrict__ out)
{
    const int i = blockIdx.x;
    const int b = blockIdx.y;
    const int t = threadIdx.x;
    const int w = t >> 5, lane = t & 31;
    const int len = cap_lens[i];

    __shared__ float att[SS][33];
    __shared__ float cw[SS][33];
    __shared__ float aw[LMAXC][SS];
    __shared__ float sG[SS * SS];
    __shared__ float rs[LMAXC];

    for (int idx = t; idx < SS * SS; idx += 256) sG[idx] = g_G[b * SS * SS + idx];

    for (int s = w; s < SS; s += 8) {
        float v = g_A[(size_t)(b * SS + s) * NCAPR + i * LMAXC + lane];
        v = v > 0.f ? v : 0.1f * v;
        if (lane >= len) v = 0.f;
        float ssq = wsum(v * v);
        att[s][lane] = v / (sqrtf(ssq) + 1e-8f);
        cw[s][lane]  = g_C[(size_t)(b * SS + s) * NCAPR + i * LMAXC + lane];
    }
    __syncthreads();

    for (int l = w; l < LMAXC; l += 8) {
        float v0 = att[lane][l];
        float v1 = (lane < 4) ? att[32 + lane][l] : 0.f;
        float z0 = 9.0f * v0;
        float z1 = (lane < 4) ? 9.0f * v1 : -1e30f;
        float m  = wmax(fmaxf(z0, z1));
        float e0 = expf(z0 - m);
        float e1 = (lane < 4) ? expf(z1 - m) : 0.f;
        float inv = 1.0f / wsum(e0 + e1);
        aw[l][lane] = e0 * inv;
        if (lane < 4) aw[l][32 + lane] = e1 * inv;
    }
    __syncthreads();

    for (int l = w; l < LMAXC; l += 8) {
        float a0 = aw[l][lane];
        float a1 = (lane < 4) ? aw[l][32 + lane] : 0.f;
        float c0 = cw[lane][l];
        float c1 = (lane < 4) ? cw[32 + lane][l] : 0.f;
        float w12 = wsum(a0 * c0 + a1 * c1);

        float t0 = 0.f, t1 = 0.f;
#pragma unroll
        for (int s = 0; s < SS; ++s) {
            float av = aw[l][s];
            t0 = fmaf(av, sG[s * SS + lane], t0);
            if (lane < 4) t1 = fmaf(av, sG[s * SS + 32 + lane], t1);
        }
        float w2sq = wsum(t0 * a0 + t1 * a1);

        if (lane == 0) {
            float denom = fmaxf(g_w1[i * LMAXC + l] * sqrtf(fmaxf(w2sq, 0.f)), 1e-8f);
            rs[l] = w12 / denom;
        }
    }
    __syncthreads();

    if (w == 0) {
        float z = (lane < len) ? rs[lane] * 6.0f : -1e30f;
        float m = wmax(z);
        float e = (lane < len) ? expf(z - m) : 0.f;
        float ssum = wsum(e);
        if (lane == 0) out[b * NB + i] = (m + logf(ssum)) / 6.0f;
    }
}

// ---------------------------------------------------------------------------
extern "C" void kernel_launch(void* const* d_in, const int* in_sizes, int n_in,
                              void* d_out, int out_size)
{
    const float* images   = (const float*)d_in[0];
    const float* captions = (const float*)d_in[1];
    const int*   cap_lens = (const int*)  d_in[2];
    const float* W_g      = (const float*)d_in[3];
    float* out = (float*)d_out;

    float *pA, *pC;
    cudaGetSymbolAddress((void**)&pA, g_A);
    cudaGetSymbolAddress((void**)&pC, g_C);
    __nv_bfloat16 *iH, *iL, *cH, *cL, *wH, *wL, *eH, *eL;
    cudaGetSymbolAddress((void**)&iH, g_imgH); cudaGetSymbolAddress((void**)&iL, g_imgL);
    cudaGetSymbolAddress((void**)&cH, g_capH); cudaGetSymbolAddress((void**)&cL, g_capL);
    cudaGetSymbolAddress((void**)&wH, g_WH);   cudaGetSymbolAddress((void**)&wL, g_WL);
    cudaGetSymbolAddress((void**)&eH, g_EH);   cudaGetSymbolAddress((void**)&eL, g_EL);

    cudaFuncSetAttribute(gemm_bulk, cudaFuncAttributeMaxDynamicSharedMemorySize, GEMM_SMEM);
    cudaFuncSetAttribute(gemm_dual, cudaFuncAttributeMaxDynamicSharedMemorySize, GEMM2_SMEM);

    // blocked + swizzled bf16 hi/lo splits of inputs
    split_blocked<<<MROWS * (DD / 8) / 256, 256>>>(images,   iH, iL, MROWS);
    split_blocked<<<NCAPR * (DD / 8) / 256, 256>>>(captions, cH, cL, NCAPR);
    split_blocked<<<DD * (DD / 8) / 256,    256>>>(W_g,      wH, wL, DD);

    // GEMM1: E = cap @ W^T -> blocked-split EH/EL directly
    gemm_bulk<<<dim3(DD / 128, NCAPR / 128), 256, GEMM_SMEM>>>(
        cH, cL, wH, wL, nullptr, eH, eL, DD);
    // GEMM2+3 fused: A = img @ E^T and C = img @ cap^T (shared img tiles)
    gemm_dual<<<dim3(NCAPR / 128, MROWS / 128), 256, GEMM2_SMEM>>>(
        iH, iL, eH, eL, cH, cL, pA, pC, NCAPR);

    // Gram + norms + fused epilogue
    zeroG_kernel<<<(NB * SS * SS + 255) / 256, 256>>>();
    gram_kernel<<<dim3(NB, 4), 256>>>(images);
    w1_kernel<<<NCAPR / 8, 256>>>(captions);
    pair_kernel<<<dim3(NB, NB), 256>>>(cap_lens, out);
}